// round 6
// baseline (speedup 1.0000x reference)
#include <cuda_runtime.h>

// ---------------------------------------------------------------------------
// Voxel2Point via occupancy-grid 3-NN (R6 = R5 re-run + finer sort key):
//   - per-batch 64^3 occupancy bitmask staged in SMEM; Chebyshev shell
//     expansion with provable stop bound
//   - per-cell linked lists with next pointer packed into g_qpos.w
//     (one LDG.128 per candidate)
//   - points spatially sorted by (batch, cz, cy, cx>>4) so warps walk
//     nearly identical shells and share L2 lines
//   - tie-aware top-3 insert == stable jax top_k; exact 4D fallback when
//     third-best d2 >= 1.0 (cross-batch candidates impossible otherwise)
// ---------------------------------------------------------------------------

#define NB     4
#define M_MAX  16384
#define N_MAX  131072
#define TPB    256
#define BPTS   256
#define MAXBLK (N_MAX / BPTS + NB)
#define BIGF   1e30f
#define CELLS  262144          // 64^3
#define BMW    8192            // bitmask words per batch (64^3 / 32)
#define BUK    65536           // sort buckets: (b, cz, cy, cx>>4)
#define BPB    16384           // buckets per batch

__device__ int    g_head[NB * CELLS];
__device__ float4 g_qpos[M_MAX];     // x,y,z = center; w = next index as float bits
__device__ unsigned int g_bm[NB * BMW];
__device__ int    g_bcnt[BUK];
__device__ int    g_bcur[BUK];
__device__ int    g_pid[N_MAX];
__device__ int    g_nblk;
__device__ int    g_dstart[MAXBLK];
__device__ int    g_dend[MAXBLK];
__device__ int    g_dbatch[MAXBLK];
__device__ int    g_idx[3 * N_MAX];
__device__ float  g_w[3 * N_MAX];

// ---- init: clear heads + bitmask + bucket counters ----
__global__ void k_init() {
    int i = blockIdx.x * blockDim.x + threadIdx.x;
    int stride = gridDim.x * blockDim.x;
    for (int k = i; k < NB * CELLS; k += stride) g_head[k] = -1;
    for (int k = i; k < NB * BMW; k += stride) g_bm[k] = 0u;
    for (int k = i; k < BUK; k += stride) g_bcnt[k] = 0;
}

// ---- build: voxel centers, linked lists (next packed in .w), bitmask ----
__global__ void k_build(const int* __restrict__ indices, int M) {
    int i = blockIdx.x * blockDim.x + threadIdx.x;
    if (i >= M) return;
    int4 v = ((const int4*)indices)[i];
    // replicate reference rounding: mul, add, add as separate ops (no FMA)
    float qx = __fadd_rn(__fadd_rn(__fmul_rn((float)v.y, 0.05f), -1.6f), 0.025f);
    float qy = __fadd_rn(__fadd_rn(__fmul_rn((float)v.z, 0.05f), -1.6f), 0.025f);
    float qz = __fadd_rn(__fadd_rn(__fmul_rn((float)v.w, 0.05f), -1.6f), 0.025f);
    int cell = (((v.w << 6) | v.z) << 6) | v.y;   // X fastest
    int old = atomicExch(&g_head[v.x * CELLS + cell], i);
    g_qpos[i] = make_float4(qx, qy, qz, __int_as_float(old));
    atomicOr(&g_bm[v.x * BMW + (cell >> 5)], 1u << (cell & 31));
}

__device__ __forceinline__ int cell_of(float v) {
    return min(63, max(0, (int)floorf(fmaf(v, 20.0f, 32.0f))));
}
__device__ __forceinline__ int key_of(int b, const float* pc, int i) {
    int cx = cell_of(pc[3 * i]);
    int cy = cell_of(pc[3 * i + 1]);
    int cz = cell_of(pc[3 * i + 2]);
    return (b << 14) | (cz << 8) | (cy << 2) | (cx >> 4);
}

// ---- spatial histogram ----
__global__ void k_histp(const float* __restrict__ pc, const int* __restrict__ bids, int N) {
    int i = blockIdx.x * blockDim.x + threadIdx.x;
    if (i < N) atomicAdd(&g_bcnt[key_of(bids[i], pc, i)], 1);
}

// ---- single-block exclusive scan over 64K buckets + block descriptors ----
// Thread t owns bucket chunk [t*256, (t+1)*256). Batch b spans thread chunks
// [b*64, (b+1)*64) since BPB = 16384 = 64 chunks of 256.
__global__ void __launch_bounds__(256) k_scan() {
    __shared__ int part[257];
    int t = threadIdx.x;
    int base = t * (BUK / 256);
    int s = 0;
    for (int k = 0; k < BUK / 256; k++) s += g_bcnt[base + k];
    part[t] = s;
    __syncthreads();
    if (t == 0) {
        int run = 0;
        for (int i = 0; i < 256; i++) { int v = part[i]; part[i] = run; run += v; }
        part[256] = run;
    }
    __syncthreads();
    int off = part[t];
    for (int k = 0; k < BUK / 256; k++) {
        int v = g_bcnt[base + k];
        g_bcur[base + k] = off;
        off += v;
    }
    __syncthreads();
    if (t == 0) {
        int dt = 0;
        for (int b = 0; b < NB; b++) {
            int cbase = part[b * 64];
            int cend  = (b + 1 < NB) ? part[(b + 1) * 64] : part[256];
            for (int k = cbase; k < cend; k += BPTS) {
                g_dstart[dt] = k;
                g_dend[dt]   = min(cend, k + BPTS);
                g_dbatch[dt] = b;
                dt++;
            }
        }
        g_nblk = dt;
    }
}

__global__ void k_scatterp(const float* __restrict__ pc, const int* __restrict__ bids, int N) {
    int i = blockIdx.x * blockDim.x + threadIdx.x;
    if (i < N) {
        int pos = atomicAdd(&g_bcur[key_of(bids[i], pc, i)], 1);
        g_pid[pos] = i;
    }
}

// tie-aware top-3 insert: (d, idx) lexicographic, matches stable jax top_k
#define INS3(dd, e)                                                          \
    do {                                                                     \
        float _d = (dd); int _e = (e);                                       \
        if (_d < D2 || (_d == D2 && _e < I2)) {                              \
            if (_d < D1 || (_d == D1 && _e < I1)) {                          \
                if (_d < D0 || (_d == D0 && _e < I0)) {                      \
                    D2 = D1; I2 = I1; D1 = D0; I1 = I0; D0 = _d; I0 = _e;    \
                } else { D2 = D1; I2 = I1; D1 = _d; I1 = _e; }               \
            } else { D2 = _d; I2 = _e; }                                     \
        }                                                                    \
    } while (0)

// test one bitmask row (z,y) against mask mk; walk lists for set bits
#define PROW(zz, yy, mk)                                                     \
    do {                                                                     \
        unsigned long long rowm =                                            \
            *(const unsigned long long*)&sbm[((((zz) << 6) + (yy)) << 1)];   \
        rowm &= (mk);                                                        \
        while (rowm) {                                                       \
            int xb = __ffsll((long long)rowm) - 1;                           \
            rowm &= rowm - 1;                                                \
            int cell = (((((zz) << 6) + (yy)) << 6) + xb);                   \
            int e = g_head[hb + cell];                                       \
            while (e >= 0) {                                                 \
                float4 qq = g_qpos[e];                                       \
                float ddx = px - qq.x, ddy = py - qq.y, ddz = pz - qq.z;     \
                float dd = fmaf(ddx, ddx, fmaf(ddy, ddy, ddz * ddz));        \
                INS3(dd, e);                                                 \
                e = __float_as_int(qq.w);                                    \
            }                                                                \
        }                                                                    \
    } while (0)

__global__ void __launch_bounds__(TPB) nn_kernel(const float* __restrict__ pc,
                                                 const int* __restrict__ indices,
                                                 int M) {
    __shared__ unsigned int sbm[BMW];
    if (blockIdx.x >= g_nblk) return;

    int b  = g_dbatch[blockIdx.x];
    int pS = g_dstart[blockIdx.x];
    int pE = g_dend[blockIdx.x];
    int hb = b * CELLS;

    for (int i = threadIdx.x; i < BMW; i += TPB) sbm[i] = g_bm[b * BMW + i];
    __syncthreads();

    int ni = pS + threadIdx.x;
    if (ni >= pE) return;
    int pid = g_pid[ni];
    float px = pc[3 * pid], py = pc[3 * pid + 1], pz = pc[3 * pid + 2];

    int cx = cell_of(px);
    int cy = cell_of(py);
    int cz = cell_of(pz);

    float D0 = BIGF, D1 = BIGF, D2 = BIGF;
    int   I0 = 0,    I1 = 0,    I2 = 0;

    for (int r = 0; r <= 63; r++) {
        if (r > 0 && D2 < BIGF) {
            float br = ((float)r - 0.5f) * 0.05f;
            if (D2 + 1e-6f < br * br) break;   // no unscanned cell can beat top-3
        }
        if (r == 0) {
            PROW(cz, cy, 1ull << cx);
            continue;
        }
        int xlo = max(cx - r, 0), xhi = min(cx + r, 63);
        unsigned long long fm =
            (xhi - xlo == 63) ? ~0ull
                              : (((1ull << (xhi - xlo + 1)) - 1ull) << xlo);
        unsigned long long pm = 0ull;
        if (cx - r >= 0)  pm |= 1ull << (cx - r);
        if (cx + r <= 63) pm |= 1ull << (cx + r);

        int ylo = max(cy - r, 0), yhi = min(cy + r, 63);
        // faces z = cz +- r : full (y,x) square
        if (cz - r >= 0)  { int z = cz - r; for (int y = ylo; y <= yhi; y++) PROW(z, y, fm); }
        if (cz + r <= 63) { int z = cz + r; for (int y = ylo; y <= yhi; y++) PROW(z, y, fm); }
        // edges y = cy +- r, |dz| < r : full x rows
        int z0 = max(cz - r + 1, 0), z1 = min(cz + r - 1, 63);
        if (cy - r >= 0)  { int y = cy - r; for (int z = z0; z <= z1; z++) PROW(z, y, fm); }
        if (cy + r <= 63) { int y = cy + r; for (int z = z0; z <= z1; z++) PROW(z, y, fm); }
        // interior: x = cx +- r only
        if (pm) {
            int y0 = max(cy - r + 1, 0), y1 = min(cy + r - 1, 63);
            for (int z = z0; z <= z1; z++)
                for (int y = y0; y <= y1; y++) PROW(z, y, pm);
        }
    }

    // fallback: exact full 4D scan (cross-batch possible only if D2 >= 1.0)
    if (D2 >= 1.0f) {
        float pb = (float)b;
        D0 = BIGF; D1 = BIGF; D2 = BIGF; I0 = 0; I1 = 0; I2 = 0;
        for (int i = 0; i < M; i++) {
            int4 v = ((const int4*)indices)[i];
            float qb = (float)v.x;
            float qx = __fadd_rn(__fadd_rn(__fmul_rn((float)v.y, 0.05f), -1.6f), 0.025f);
            float qy = __fadd_rn(__fadd_rn(__fmul_rn((float)v.z, 0.05f), -1.6f), 0.025f);
            float qz = __fadd_rn(__fadd_rn(__fmul_rn((float)v.w, 0.05f), -1.6f), 0.025f);
            float dx = px - qx, dy = py - qy, dz = pz - qz, db = pb - qb;
            float dd = fmaf(dx, dx, fmaf(dy, dy, fmaf(dz, dz, db * db)));
            INS3(dd, i);
        }
    }

    float r0 = 1.0f / (D0 + 1e-8f);
    float r1 = 1.0f / (D1 + 1e-8f);
    float r2 = 1.0f / (D2 + 1e-8f);
    float s = r0 + r1 + r2;
    g_w[3 * pid + 0] = r0 / s;
    g_w[3 * pid + 1] = r1 / s;
    g_w[3 * pid + 2] = r2 / s;
    g_idx[3 * pid + 0] = I0;
    g_idx[3 * pid + 1] = I1;
    g_idx[3 * pid + 2] = I2;
}

// ---- weighted gather-interpolate ----
__global__ void interp_kernel(const float* __restrict__ feats,
                              float* __restrict__ out, int N, int C) {
    int C4 = C >> 2;
    int t = blockIdx.x * blockDim.x + threadIdx.x;
    int n, c;
    if (C4 == 16) { n = t >> 4; c = t & 15; }
    else          { n = t / C4; c = t % C4; }
    if (n >= N) return;

    int i0 = g_idx[3 * n + 0];
    int i1 = g_idx[3 * n + 1];
    int i2 = g_idx[3 * n + 2];
    float w0 = g_w[3 * n + 0];
    float w1 = g_w[3 * n + 1];
    float w2 = g_w[3 * n + 2];

    const float4* f = (const float4*)feats;
    float4 a = f[i0 * C4 + c];
    float4 b = f[i1 * C4 + c];
    float4 d = f[i2 * C4 + c];
    float4 o;
    o.x = w0 * a.x + w1 * b.x + w2 * d.x;
    o.y = w0 * a.y + w1 * b.y + w2 * d.y;
    o.z = w0 * a.z + w1 * b.z + w2 * d.z;
    o.w = w0 * a.w + w1 * b.w + w2 * d.w;
    ((float4*)out)[n * C4 + c] = o;
}

extern "C" void kernel_launch(void* const* d_in, const int* in_sizes, int n_in,
                              void* d_out, int out_size) {
    const float* features = (const float*)d_in[0];  // (M, C) f32
    const int*   indices  = (const int*)d_in[1];    // (M, 4) i32
    const float* pc       = (const float*)d_in[2];  // (N, 3) f32
    const int*   bids     = (const int*)d_in[3];    // (N,)   i32

    int M = in_sizes[1] / 4;
    int C = in_sizes[0] / M;
    int N = in_sizes[3];

    k_init<<<1024, 256>>>();
    k_build<<<(M + 255) / 256, 256>>>(indices, M);
    k_histp<<<(N + 255) / 256, 256>>>(pc, bids, N);
    k_scan<<<1, 256>>>();
    k_scatterp<<<(N + 255) / 256, 256>>>(pc, bids, N);

    int maxblk = (N + BPTS - 1) / BPTS + NB;
    nn_kernel<<<maxblk, TPB>>>(pc, indices, M);

    int C4 = C >> 2;
    interp_kernel<<<(N * C4 + 255) / 256, 256>>>(features, (float*)d_out, N, C);
}

// round 8
// speedup vs baseline: 1.5548x; 1.5548x over previous
#include <cuda_runtime.h>

// ---------------------------------------------------------------------------
// Voxel2Point via occupancy-grid 3-NN (R8 = R7 with scan barrier-race fixed):
//   - per-batch 64^3 occupancy bitmask staged in SMEM; Chebyshev shell
//     expansion with provable stop bound
//   - per-cell linked lists with next pointer packed into g_qpos.w
//   - points spatially sorted by (batch, cz, cy, cx>>4); offsets via
//     chip-wide 3-stage hierarchical scan (race-free Hillis-Steele)
//   - tie-aware top-3 insert == stable jax top_k; exact 4D fallback when
//     third-best d2 >= 1.0 (cross-batch candidates impossible otherwise)
// ---------------------------------------------------------------------------

#define NB     4
#define M_MAX  16384
#define N_MAX  131072
#define TPB    256
#define BPTS   256
#define MAXBLK (N_MAX / BPTS + NB)
#define BIGF   1e30f
#define CELLS  262144          // 64^3
#define BMW    8192            // bitmask words per batch (64^3 / 32)
#define BUK    65536           // sort buckets: (b, cz, cy, cx>>4)
#define NPART  256             // scan partitions (BUK / 256)

__device__ int    g_head[NB * CELLS];
__device__ float4 g_qpos[M_MAX];     // x,y,z = center; w = next index as float bits
__device__ unsigned int g_bm[NB * BMW];
__device__ int    g_bcnt[BUK];
__device__ int    g_bcur[BUK];
__device__ int    g_part[NPART];
__device__ int    g_partoff[NPART + 1];
__device__ int    g_pid[N_MAX];
__device__ int    g_nblk;
__device__ int    g_dstart[MAXBLK];
__device__ int    g_dend[MAXBLK];
__device__ int    g_dbatch[MAXBLK];
__device__ int    g_idx[3 * N_MAX];
__device__ float  g_w[3 * N_MAX];

// ---- init: clear heads + bitmask + bucket counters ----
__global__ void k_init() {
    int i = blockIdx.x * blockDim.x + threadIdx.x;
    int stride = gridDim.x * blockDim.x;
    for (int k = i; k < NB * CELLS; k += stride) g_head[k] = -1;
    for (int k = i; k < NB * BMW; k += stride) g_bm[k] = 0u;
    for (int k = i; k < BUK; k += stride) g_bcnt[k] = 0;
}

// ---- build: voxel centers, linked lists (next packed in .w), bitmask ----
__global__ void k_build(const int* __restrict__ indices, int M) {
    int i = blockIdx.x * blockDim.x + threadIdx.x;
    if (i >= M) return;
    int4 v = ((const int4*)indices)[i];
    // replicate reference rounding: mul, add, add as separate ops (no FMA)
    float qx = __fadd_rn(__fadd_rn(__fmul_rn((float)v.y, 0.05f), -1.6f), 0.025f);
    float qy = __fadd_rn(__fadd_rn(__fmul_rn((float)v.z, 0.05f), -1.6f), 0.025f);
    float qz = __fadd_rn(__fadd_rn(__fmul_rn((float)v.w, 0.05f), -1.6f), 0.025f);
    int cell = (((v.w << 6) | v.z) << 6) | v.y;   // X fastest
    int old = atomicExch(&g_head[v.x * CELLS + cell], i);
    g_qpos[i] = make_float4(qx, qy, qz, __int_as_float(old));
    atomicOr(&g_bm[v.x * BMW + (cell >> 5)], 1u << (cell & 31));
}

__device__ __forceinline__ int cell_of(float v) {
    return min(63, max(0, (int)floorf(fmaf(v, 20.0f, 32.0f))));
}
__device__ __forceinline__ int key_of(int b, const float* pc, int i) {
    int cx = cell_of(pc[3 * i]);
    int cy = cell_of(pc[3 * i + 1]);
    int cz = cell_of(pc[3 * i + 2]);
    return (b << 14) | (cz << 8) | (cy << 2) | (cx >> 4);
}

// ---- spatial histogram ----
__global__ void k_histp(const float* __restrict__ pc, const int* __restrict__ bids, int N) {
    int i = blockIdx.x * blockDim.x + threadIdx.x;
    if (i < N) atomicAdd(&g_bcnt[key_of(bids[i], pc, i)], 1);
}

// ---- scan stage 1: per-partition sums (256 blocks x 256 threads) ----
__global__ void __launch_bounds__(256) k_part() {
    __shared__ int s[256];
    int t = threadIdx.x;
    s[t] = g_bcnt[blockIdx.x * 256 + t];
    __syncthreads();
    for (int o = 128; o > 0; o >>= 1) {
        if (t < o) s[t] += s[t + o];
        __syncthreads();
    }
    if (t == 0) g_part[blockIdx.x] = s[0];
}

// ---- scan stage 2: exclusive scan of 256 partials + block descriptors ----
__global__ void __launch_bounds__(256) k_top() {
    __shared__ int s[257];
    int t = threadIdx.x;
    s[t] = g_part[t];
    __syncthreads();
    // race-free Hillis-Steele: read, sync, accumulate, sync
    for (int o = 1; o < 256; o <<= 1) {
        int v = (t >= o) ? s[t - o] : 0;
        __syncthreads();
        s[t] += v;
        __syncthreads();
    }
    int total = s[255];
    int excl = (t == 0) ? 0 : s[t - 1];
    __syncthreads();
    s[t] = excl;
    if (t == 0) s[256] = total;
    g_partoff[t] = excl;
    if (t == 0) g_partoff[256] = total;
    __syncthreads();
    if (t == 0) {
        // batch b spans part chunks [b*64, (b+1)*64)  (BUK/NB = 16384 = 64*256)
        int dt = 0;
        for (int b = 0; b < NB; b++) {
            int cbase = s[b * 64];
            int cend  = s[(b + 1) * 64];
            for (int k = cbase; k < cend; k += BPTS) {
                g_dstart[dt] = k;
                g_dend[dt]   = min(cend, k + BPTS);
                g_dbatch[dt] = b;
                dt++;
            }
        }
        g_nblk = dt;
    }
}

// ---- scan stage 3: per-bucket exclusive offsets (256 blocks x 256 threads) ----
__global__ void __launch_bounds__(256) k_off() {
    __shared__ int s[256];
    int t = threadIdx.x;
    int base = blockIdx.x * 256;
    int v0 = g_bcnt[base + t];
    s[t] = v0;
    __syncthreads();
    for (int o = 1; o < 256; o <<= 1) {
        int v = (t >= o) ? s[t - o] : 0;
        __syncthreads();
        s[t] += v;
        __syncthreads();
    }
    g_bcur[base + t] = g_partoff[blockIdx.x] + s[t] - v0;   // inclusive - self
}

__global__ void k_scatterp(const float* __restrict__ pc, const int* __restrict__ bids, int N) {
    int i = blockIdx.x * blockDim.x + threadIdx.x;
    if (i < N) {
        int pos = atomicAdd(&g_bcur[key_of(bids[i], pc, i)], 1);
        g_pid[pos] = i;
    }
}

// tie-aware top-3 insert: (d, idx) lexicographic, matches stable jax top_k
#define INS3(dd, e)                                                          \
    do {                                                                     \
        float _d = (dd); int _e = (e);                                       \
        if (_d < D2 || (_d == D2 && _e < I2)) {                              \
            if (_d < D1 || (_d == D1 && _e < I1)) {                          \
                if (_d < D0 || (_d == D0 && _e < I0)) {                      \
                    D2 = D1; I2 = I1; D1 = D0; I1 = I0; D0 = _d; I0 = _e;    \
                } else { D2 = D1; I2 = I1; D1 = _d; I1 = _e; }               \
            } else { D2 = _d; I2 = _e; }                                     \
        }                                                                    \
    } while (0)

// test one bitmask row (z,y) against mask mk; walk lists for set bits
#define PROW(zz, yy, mk)                                                     \
    do {                                                                     \
        unsigned long long rowm =                                            \
            *(const unsigned long long*)&sbm[((((zz) << 6) + (yy)) << 1)];   \
        rowm &= (mk);                                                        \
        while (rowm) {                                                       \
            int xb = __ffsll((long long)rowm) - 1;                           \
            rowm &= rowm - 1;                                                \
            int cell = (((((zz) << 6) + (yy)) << 6) + xb);                   \
            int e = g_head[hb + cell];                                       \
            while (e >= 0) {                                                 \
                float4 qq = g_qpos[e];                                       \
                float ddx = px - qq.x, ddy = py - qq.y, ddz = pz - qq.z;     \
                float dd = fmaf(ddx, ddx, fmaf(ddy, ddy, ddz * ddz));        \
                INS3(dd, e);                                                 \
                e = __float_as_int(qq.w);                                    \
            }                                                                \
        }                                                                    \
    } while (0)

__global__ void __launch_bounds__(TPB) nn_kernel(const float* __restrict__ pc,
                                                 const int* __restrict__ indices,
                                                 int M) {
    __shared__ unsigned int sbm[BMW];
    if (blockIdx.x >= g_nblk) return;

    int b  = g_dbatch[blockIdx.x];
    int pS = g_dstart[blockIdx.x];
    int pE = g_dend[blockIdx.x];
    int hb = b * CELLS;

    for (int i = threadIdx.x; i < BMW; i += TPB) sbm[i] = g_bm[b * BMW + i];
    __syncthreads();

    int ni = pS + threadIdx.x;
    if (ni >= pE) return;
    int pid = g_pid[ni];
    float px = pc[3 * pid], py = pc[3 * pid + 1], pz = pc[3 * pid + 2];

    int cx = cell_of(px);
    int cy = cell_of(py);
    int cz = cell_of(pz);

    float D0 = BIGF, D1 = BIGF, D2 = BIGF;
    int   I0 = 0,    I1 = 0,    I2 = 0;

    for (int r = 0; r <= 63; r++) {
        if (r > 0 && D2 < BIGF) {
            float br = ((float)r - 0.5f) * 0.05f;
            if (D2 + 1e-6f < br * br) break;   // no unscanned cell can beat top-3
        }
        if (r == 0) {
            PROW(cz, cy, 1ull << cx);
            continue;
        }
        int xlo = max(cx - r, 0), xhi = min(cx + r, 63);
        unsigned long long fm =
            (xhi - xlo == 63) ? ~0ull
                              : (((1ull << (xhi - xlo + 1)) - 1ull) << xlo);
        unsigned long long pm = 0ull;
        if (cx - r >= 0)  pm |= 1ull << (cx - r);
        if (cx + r <= 63) pm |= 1ull << (cx + r);

        int ylo = max(cy - r, 0), yhi = min(cy + r, 63);
        // faces z = cz +- r : full (y,x) square
        if (cz - r >= 0)  { int z = cz - r; for (int y = ylo; y <= yhi; y++) PROW(z, y, fm); }
        if (cz + r <= 63) { int z = cz + r; for (int y = ylo; y <= yhi; y++) PROW(z, y, fm); }
        // edges y = cy +- r, |dz| < r : full x rows
        int z0 = max(cz - r + 1, 0), z1 = min(cz + r - 1, 63);
        if (cy - r >= 0)  { int y = cy - r; for (int z = z0; z <= z1; z++) PROW(z, y, fm); }
        if (cy + r <= 63) { int y = cy + r; for (int z = z0; z <= z1; z++) PROW(z, y, fm); }
        // interior: x = cx +- r only
        if (pm) {
            int y0 = max(cy - r + 1, 0), y1 = min(cy + r - 1, 63);
            for (int z = z0; z <= z1; z++)
                for (int y = y0; y <= y1; y++) PROW(z, y, pm);
        }
    }

    // fallback: exact full 4D scan (cross-batch possible only if D2 >= 1.0)
    if (D2 >= 1.0f) {
        float pb = (float)b;
        D0 = BIGF; D1 = BIGF; D2 = BIGF; I0 = 0; I1 = 0; I2 = 0;
        for (int i = 0; i < M; i++) {
            int4 v = ((const int4*)indices)[i];
            float qb = (float)v.x;
            float qx = __fadd_rn(__fadd_rn(__fmul_rn((float)v.y, 0.05f), -1.6f), 0.025f);
            float qy = __fadd_rn(__fadd_rn(__fmul_rn((float)v.z, 0.05f), -1.6f), 0.025f);
            float qz = __fadd_rn(__fadd_rn(__fmul_rn((float)v.w, 0.05f), -1.6f), 0.025f);
            float dx = px - qx, dy = py - qy, dz = pz - qz, db = pb - qb;
            float dd = fmaf(dx, dx, fmaf(dy, dy, fmaf(dz, dz, db * db)));
            INS3(dd, i);
        }
    }

    float r0 = 1.0f / (D0 + 1e-8f);
    float r1 = 1.0f / (D1 + 1e-8f);
    float r2 = 1.0f / (D2 + 1e-8f);
    float s = r0 + r1 + r2;
    g_w[3 * pid + 0] = r0 / s;
    g_w[3 * pid + 1] = r1 / s;
    g_w[3 * pid + 2] = r2 / s;
    g_idx[3 * pid + 0] = I0;
    g_idx[3 * pid + 1] = I1;
    g_idx[3 * pid + 2] = I2;
}

// ---- weighted gather-interpolate ----
__global__ void interp_kernel(const float* __restrict__ feats,
                              float* __restrict__ out, int N, int C) {
    int C4 = C >> 2;
    int t = blockIdx.x * blockDim.x + threadIdx.x;
    int n, c;
    if (C4 == 16) { n = t >> 4; c = t & 15; }
    else          { n = t / C4; c = t % C4; }
    if (n >= N) return;

    int i0 = g_idx[3 * n + 0];
    int i1 = g_idx[3 * n + 1];
    int i2 = g_idx[3 * n + 2];
    float w0 = g_w[3 * n + 0];
    float w1 = g_w[3 * n + 1];
    float w2 = g_w[3 * n + 2];

    const float4* f = (const float4*)feats;
    float4 a = f[i0 * C4 + c];
    float4 b = f[i1 * C4 + c];
    float4 d = f[i2 * C4 + c];
    float4 o;
    o.x = w0 * a.x + w1 * b.x + w2 * d.x;
    o.y = w0 * a.y + w1 * b.y + w2 * d.y;
    o.z = w0 * a.z + w1 * b.z + w2 * d.z;
    o.w = w0 * a.w + w1 * b.w + w2 * d.w;
    ((float4*)out)[n * C4 + c] = o;
}

extern "C" void kernel_launch(void* const* d_in, const int* in_sizes, int n_in,
                              void* d_out, int out_size) {
    const float* features = (const float*)d_in[0];  // (M, C) f32
    const int*   indices  = (const int*)d_in[1];    // (M, 4) i32
    const float* pc       = (const float*)d_in[2];  // (N, 3) f32
    const int*   bids     = (const int*)d_in[3];    // (N,)   i32

    int M = in_sizes[1] / 4;
    int C = in_sizes[0] / M;
    int N = in_sizes[3];

    k_init<<<1024, 256>>>();
    k_build<<<(M + 255) / 256, 256>>>(indices, M);
    k_histp<<<(N + 255) / 256, 256>>>(pc, bids, N);
    k_part<<<NPART, 256>>>();
    k_top<<<1, 256>>>();
    k_off<<<NPART, 256>>>();
    k_scatterp<<<(N + 255) / 256, 256>>>(pc, bids, N);

    int maxblk = (N + BPTS - 1) / BPTS + NB;
    nn_kernel<<<maxblk, TPB>>>(pc, indices, M);

    int C4 = C >> 2;
    interp_kernel<<<(N * C4 + 255) / 256, 256>>>(features, (float*)d_out, N, C);
}

// round 9
// speedup vs baseline: 1.7545x; 1.1284x over previous
#include <cuda_runtime.h>

// ---------------------------------------------------------------------------
// Voxel2Point via occupancy-grid 3-NN (R9 = R8 + direct-mapped cell array):
//   - per-batch 64^3 occupancy bitmask staged in SMEM; Chebyshev shell
//     expansion with provable stop bound
//   - g_cell[b][cell] = (x,y,z, idx|flag): head entry position + original
//     index in ONE independent LDG.128 (no g_head->g_qpos chain); duplicate
//     cells (flag bit 30) continue via the g_qpos linked chain (rare)
//   - g_cell needs no init: bitmask guards every read
//   - points spatially sorted by (batch, cz, cy, cx>>4) via race-free
//     3-stage hierarchical scan
//   - tie-aware top-3 insert == stable jax top_k; exact 4D fallback when
//     third-best d2 >= 1.0 (cross-batch candidates impossible otherwise)
// ---------------------------------------------------------------------------

#define NB     4
#define M_MAX  16384
#define N_MAX  131072
#define TPB    256
#define BPTS   256
#define MAXBLK (N_MAX / BPTS + NB)
#define BIGF   1e30f
#define CELLS  262144          // 64^3
#define BMW    8192            // bitmask words per batch (64^3 / 32)
#define BUK    65536           // sort buckets: (b, cz, cy, cx>>4)
#define NPART  256             // scan partitions (BUK / 256)
#define CHAINF 0x40000000      // "cell has more entries" flag in g_cell.w
#define IDXM   0x3FFF          // index mask (M <= 16384)

__device__ int    g_head[NB * CELLS];
__device__ float4 g_qpos[M_MAX];     // x,y,z = center; w = next index as float bits
__device__ float4 g_cell[NB * CELLS]; // head entry: x,y,z, (idx | flag) — bitmask-guarded, no init
__device__ unsigned int g_bm[NB * BMW];
__device__ int    g_bcnt[BUK];
__device__ int    g_bcur[BUK];
__device__ int    g_part[NPART];
__device__ int    g_partoff[NPART + 1];
__device__ int    g_pid[N_MAX];
__device__ int    g_nblk;
__device__ int    g_dstart[MAXBLK];
__device__ int    g_dend[MAXBLK];
__device__ int    g_dbatch[MAXBLK];
__device__ int    g_idx[3 * N_MAX];
__device__ float  g_w[3 * N_MAX];

// ---- init: clear heads + bitmask + bucket counters ----
__global__ void k_init() {
    int i = blockIdx.x * blockDim.x + threadIdx.x;
    int stride = gridDim.x * blockDim.x;
    for (int k = i; k < NB * CELLS; k += stride) g_head[k] = -1;
    for (int k = i; k < NB * BMW; k += stride) g_bm[k] = 0u;
    for (int k = i; k < BUK; k += stride) g_bcnt[k] = 0;
}

// ---- build: voxel centers, linked lists (next packed in .w), bitmask ----
__global__ void k_build(const int* __restrict__ indices, int M) {
    int i = blockIdx.x * blockDim.x + threadIdx.x;
    if (i >= M) return;
    int4 v = ((const int4*)indices)[i];
    // replicate reference rounding: mul, add, add as separate ops (no FMA)
    float qx = __fadd_rn(__fadd_rn(__fmul_rn((float)v.y, 0.05f), -1.6f), 0.025f);
    float qy = __fadd_rn(__fadd_rn(__fmul_rn((float)v.z, 0.05f), -1.6f), 0.025f);
    float qz = __fadd_rn(__fadd_rn(__fmul_rn((float)v.w, 0.05f), -1.6f), 0.025f);
    int cell = (((v.w << 6) | v.z) << 6) | v.y;   // X fastest
    int old = atomicExch(&g_head[v.x * CELLS + cell], i);
    g_qpos[i] = make_float4(qx, qy, qz, __int_as_float(old));
    atomicOr(&g_bm[v.x * BMW + (cell >> 5)], 1u << (cell & 31));
}

// ---- compact: head entry of each occupied cell -> direct-mapped g_cell ----
__global__ void k_compact(const int* __restrict__ indices, int M) {
    int i = blockIdx.x * blockDim.x + threadIdx.x;
    if (i >= M) return;
    int4 v = ((const int4*)indices)[i];
    int cell = (((v.w << 6) | v.z) << 6) | v.y;
    int slot = v.x * CELLS + cell;
    if (g_head[slot] == i) {
        float4 q = g_qpos[i];
        int next = __float_as_int(q.w);
        int wbits = i | (next >= 0 ? CHAINF : 0);
        g_cell[slot] = make_float4(q.x, q.y, q.z, __int_as_float(wbits));
    }
}

__device__ __forceinline__ int cell_of(float v) {
    return min(63, max(0, (int)floorf(fmaf(v, 20.0f, 32.0f))));
}
__device__ __forceinline__ int key_of(int b, const float* pc, int i) {
    int cx = cell_of(pc[3 * i]);
    int cy = cell_of(pc[3 * i + 1]);
    int cz = cell_of(pc[3 * i + 2]);
    return (b << 14) | (cz << 8) | (cy << 2) | (cx >> 4);
}

// ---- spatial histogram ----
__global__ void k_histp(const float* __restrict__ pc, const int* __restrict__ bids, int N) {
    int i = blockIdx.x * blockDim.x + threadIdx.x;
    if (i < N) atomicAdd(&g_bcnt[key_of(bids[i], pc, i)], 1);
}

// ---- scan stage 1: per-partition sums ----
__global__ void __launch_bounds__(256) k_part() {
    __shared__ int s[256];
    int t = threadIdx.x;
    s[t] = g_bcnt[blockIdx.x * 256 + t];
    __syncthreads();
    for (int o = 128; o > 0; o >>= 1) {
        if (t < o) s[t] += s[t + o];
        __syncthreads();
    }
    if (t == 0) g_part[blockIdx.x] = s[0];
}

// ---- scan stage 2: exclusive scan of partials + block descriptors ----
__global__ void __launch_bounds__(256) k_top() {
    __shared__ int s[257];
    int t = threadIdx.x;
    s[t] = g_part[t];
    __syncthreads();
    for (int o = 1; o < 256; o <<= 1) {     // race-free Hillis-Steele
        int v = (t >= o) ? s[t - o] : 0;
        __syncthreads();
        s[t] += v;
        __syncthreads();
    }
    int total = s[255];
    int excl = (t == 0) ? 0 : s[t - 1];
    __syncthreads();
    s[t] = excl;
    if (t == 0) s[256] = total;
    g_partoff[t] = excl;
    if (t == 0) g_partoff[256] = total;
    __syncthreads();
    if (t == 0) {
        int dt = 0;
        for (int b = 0; b < NB; b++) {
            int cbase = s[b * 64];
            int cend  = s[(b + 1) * 64];
            for (int k = cbase; k < cend; k += BPTS) {
                g_dstart[dt] = k;
                g_dend[dt]   = min(cend, k + BPTS);
                g_dbatch[dt] = b;
                dt++;
            }
        }
        g_nblk = dt;
    }
}

// ---- scan stage 3: per-bucket exclusive offsets ----
__global__ void __launch_bounds__(256) k_off() {
    __shared__ int s[256];
    int t = threadIdx.x;
    int base = blockIdx.x * 256;
    int v0 = g_bcnt[base + t];
    s[t] = v0;
    __syncthreads();
    for (int o = 1; o < 256; o <<= 1) {
        int v = (t >= o) ? s[t - o] : 0;
        __syncthreads();
        s[t] += v;
        __syncthreads();
    }
    g_bcur[base + t] = g_partoff[blockIdx.x] + s[t] - v0;
}

__global__ void k_scatterp(const float* __restrict__ pc, const int* __restrict__ bids, int N) {
    int i = blockIdx.x * blockDim.x + threadIdx.x;
    if (i < N) {
        int pos = atomicAdd(&g_bcur[key_of(bids[i], pc, i)], 1);
        g_pid[pos] = i;
    }
}

// tie-aware top-3 insert: (d, idx) lexicographic, matches stable jax top_k
#define INS3(dd, e)                                                          \
    do {                                                                     \
        float _d = (dd); int _e = (e);                                       \
        if (_d < D2 || (_d == D2 && _e < I2)) {                              \
            if (_d < D1 || (_d == D1 && _e < I1)) {                          \
                if (_d < D0 || (_d == D0 && _e < I0)) {                      \
                    D2 = D1; I2 = I1; D1 = D0; I1 = I0; D0 = _d; I0 = _e;    \
                } else { D2 = D1; I2 = I1; D1 = _d; I1 = _e; }               \
            } else { D2 = _d; I2 = _e; }                                     \
        }                                                                    \
    } while (0)

// test one bitmask row (z,y) against mask mk; direct-mapped cell lookups
#define PROW(zz, yy, mk)                                                     \
    do {                                                                     \
        unsigned long long rowm =                                            \
            *(const unsigned long long*)&sbm[((((zz) << 6) + (yy)) << 1)];   \
        rowm &= (mk);                                                        \
        while (rowm) {                                                       \
            int xb = __ffsll((long long)rowm) - 1;                           \
            rowm &= rowm - 1;                                                \
            int cell = (((((zz) << 6) + (yy)) << 6) + xb);                   \
            float4 qq = g_cell[hb + cell];                                   \
            int wi = __float_as_int(qq.w);                                   \
            int qi = wi & IDXM;                                              \
            float ddx = px - qq.x, ddy = py - qq.y, ddz = pz - qq.z;         \
            float dd = fmaf(ddx, ddx, fmaf(ddy, ddy, ddz * ddz));            \
            INS3(dd, qi);                                                    \
            if (wi & CHAINF) {                                               \
                int e = __float_as_int(g_qpos[qi].w);                        \
                while (e >= 0) {                                             \
                    float4 q2 = g_qpos[e];                                   \
                    float ex = px - q2.x, ey = py - q2.y, ez = pz - q2.z;    \
                    float d2c = fmaf(ex, ex, fmaf(ey, ey, ez * ez));         \
                    INS3(d2c, e);                                            \
                    e = __float_as_int(q2.w);                                \
                }                                                            \
            }                                                                \
        }                                                                    \
    } while (0)

__global__ void __launch_bounds__(TPB) nn_kernel(const float* __restrict__ pc,
                                                 const int* __restrict__ indices,
                                                 int M) {
    __shared__ unsigned int sbm[BMW];
    if (blockIdx.x >= g_nblk) return;

    int b  = g_dbatch[blockIdx.x];
    int pS = g_dstart[blockIdx.x];
    int pE = g_dend[blockIdx.x];
    int hb = b * CELLS;

    for (int i = threadIdx.x; i < BMW; i += TPB) sbm[i] = g_bm[b * BMW + i];
    __syncthreads();

    int ni = pS + threadIdx.x;
    if (ni >= pE) return;
    int pid = g_pid[ni];
    float px = pc[3 * pid], py = pc[3 * pid + 1], pz = pc[3 * pid + 2];

    int cx = cell_of(px);
    int cy = cell_of(py);
    int cz = cell_of(pz);

    float D0 = BIGF, D1 = BIGF, D2 = BIGF;
    int   I0 = 0,    I1 = 0,    I2 = 0;

    for (int r = 0; r <= 63; r++) {
        if (r > 0 && D2 < BIGF) {
            float br = ((float)r - 0.5f) * 0.05f;
            if (D2 + 1e-6f < br * br) break;   // no unscanned cell can beat top-3
        }
        if (r == 0) {
            PROW(cz, cy, 1ull << cx);
            continue;
        }
        int xlo = max(cx - r, 0), xhi = min(cx + r, 63);
        unsigned long long fm =
            (xhi - xlo == 63) ? ~0ull
                              : (((1ull << (xhi - xlo + 1)) - 1ull) << xlo);
        unsigned long long pm = 0ull;
        if (cx - r >= 0)  pm |= 1ull << (cx - r);
        if (cx + r <= 63) pm |= 1ull << (cx + r);

        int ylo = max(cy - r, 0), yhi = min(cy + r, 63);
        // faces z = cz +- r : full (y,x) square
        if (cz - r >= 0)  { int z = cz - r; for (int y = ylo; y <= yhi; y++) PROW(z, y, fm); }
        if (cz + r <= 63) { int z = cz + r; for (int y = ylo; y <= yhi; y++) PROW(z, y, fm); }
        // edges y = cy +- r, |dz| < r : full x rows
        int z0 = max(cz - r + 1, 0), z1 = min(cz + r - 1, 63);
        if (cy - r >= 0)  { int y = cy - r; for (int z = z0; z <= z1; z++) PROW(z, y, fm); }
        if (cy + r <= 63) { int y = cy + r; for (int z = z0; z <= z1; z++) PROW(z, y, fm); }
        // interior: x = cx +- r only
        if (pm) {
            int y0 = max(cy - r + 1, 0), y1 = min(cy + r - 1, 63);
            for (int z = z0; z <= z1; z++)
                for (int y = y0; y <= y1; y++) PROW(z, y, pm);
        }
    }

    // fallback: exact full 4D scan (cross-batch possible only if D2 >= 1.0)
    if (D2 >= 1.0f) {
        float pb = (float)b;
        D0 = BIGF; D1 = BIGF; D2 = BIGF; I0 = 0; I1 = 0; I2 = 0;
        for (int i = 0; i < M; i++) {
            int4 v = ((const int4*)indices)[i];
            float qb = (float)v.x;
            float qx = __fadd_rn(__fadd_rn(__fmul_rn((float)v.y, 0.05f), -1.6f), 0.025f);
            float qy = __fadd_rn(__fadd_rn(__fmul_rn((float)v.z, 0.05f), -1.6f), 0.025f);
            float qz = __fadd_rn(__fadd_rn(__fmul_rn((float)v.w, 0.05f), -1.6f), 0.025f);
            float dx = px - qx, dy = py - qy, dz = pz - qz, db = pb - qb;
            float dd = fmaf(dx, dx, fmaf(dy, dy, fmaf(dz, dz, db * db)));
            INS3(dd, i);
        }
    }

    float r0 = 1.0f / (D0 + 1e-8f);
    float r1 = 1.0f / (D1 + 1e-8f);
    float r2 = 1.0f / (D2 + 1e-8f);
    float s = r0 + r1 + r2;
    g_w[3 * pid + 0] = r0 / s;
    g_w[3 * pid + 1] = r1 / s;
    g_w[3 * pid + 2] = r2 / s;
    g_idx[3 * pid + 0] = I0;
    g_idx[3 * pid + 1] = I1;
    g_idx[3 * pid + 2] = I2;
}

// ---- weighted gather-interpolate ----
__global__ void interp_kernel(const float* __restrict__ feats,
                              float* __restrict__ out, int N, int C) {
    int C4 = C >> 2;
    int t = blockIdx.x * blockDim.x + threadIdx.x;
    int n, c;
    if (C4 == 16) { n = t >> 4; c = t & 15; }
    else          { n = t / C4; c = t % C4; }
    if (n >= N) return;

    int i0 = g_idx[3 * n + 0];
    int i1 = g_idx[3 * n + 1];
    int i2 = g_idx[3 * n + 2];
    float w0 = g_w[3 * n + 0];
    float w1 = g_w[3 * n + 1];
    float w2 = g_w[3 * n + 2];

    const float4* f = (const float4*)feats;
    float4 a = f[i0 * C4 + c];
    float4 b = f[i1 * C4 + c];
    float4 d = f[i2 * C4 + c];
    float4 o;
    o.x = w0 * a.x + w1 * b.x + w2 * d.x;
    o.y = w0 * a.y + w1 * b.y + w2 * d.y;
    o.z = w0 * a.z + w1 * b.z + w2 * d.z;
    o.w = w0 * a.w + w1 * b.w + w2 * d.w;
    ((float4*)out)[n * C4 + c] = o;
}

extern "C" void kernel_launch(void* const* d_in, const int* in_sizes, int n_in,
                              void* d_out, int out_size) {
    const float* features = (const float*)d_in[0];  // (M, C) f32
    const int*   indices  = (const int*)d_in[1];    // (M, 4) i32
    const float* pc       = (const float*)d_in[2];  // (N, 3) f32
    const int*   bids     = (const int*)d_in[3];    // (N,)   i32

    int M = in_sizes[1] / 4;
    int C = in_sizes[0] / M;
    int N = in_sizes[3];

    k_init<<<1024, 256>>>();
    k_build<<<(M + 255) / 256, 256>>>(indices, M);
    k_compact<<<(M + 255) / 256, 256>>>(indices, M);
    k_histp<<<(N + 255) / 256, 256>>>(pc, bids, N);
    k_part<<<NPART, 256>>>();
    k_top<<<1, 256>>>();
    k_off<<<NPART, 256>>>();
    k_scatterp<<<(N + 255) / 256, 256>>>(pc, bids, N);

    int maxblk = (N + BPTS - 1) / BPTS + NB;
    nn_kernel<<<maxblk, TPB>>>(pc, indices, M);

    int C4 = C >> 2;
    interp_kernel<<<(N * C4 + 255) / 256, 256>>>(features, (float*)d_out, N, C);
}

// round 10
// speedup vs baseline: 1.8834x; 1.0735x over previous
#include <cuda_runtime.h>

// ---------------------------------------------------------------------------
// Voxel2Point via occupancy-grid 3-NN (R10 = R9 + bigger nn blocks, packed
// interp metadata, fused build+hist):
//   - per-batch 64^3 occupancy bitmask staged in SMEM (uint4 loads);
//     Chebyshev shell expansion with provable stop bound
//   - g_cell[b][cell] = (x,y,z, idx|flag): one independent LDG.128 per
//     candidate cell; duplicate cells chain through g_qpos (rare)
//   - points spatially sorted by (batch, cz, cy, cx>>4) via race-free scan
//   - nn writes packed int4 indices + float4 weights; interp uses 8
//     threads/point with 2 gather chains each
// ---------------------------------------------------------------------------

#define NB     4
#define M_MAX  16384
#define N_MAX  131072
#define TPB    512
#define BPTS   512
#define MAXBLK (N_MAX / BPTS + NB)
#define BIGF   1e30f
#define CELLS  262144          // 64^3
#define BMW    8192            // bitmask words per batch (64^3 / 32)
#define BUK    65536           // sort buckets: (b, cz, cy, cx>>4)
#define NPART  256             // scan partitions (BUK / 256)
#define CHAINF 0x40000000      // "cell has more entries" flag in g_cell.w
#define IDXM   0x3FFF          // index mask (M <= 16384)

__device__ int    g_head[NB * CELLS];
__device__ float4 g_qpos[M_MAX];      // x,y,z = center; w = next index bits
__device__ float4 g_cell[NB * CELLS]; // head entry — bitmask-guarded, no init
__device__ unsigned int g_bm[NB * BMW];
__device__ int    g_bcnt[BUK];
__device__ int    g_bcur[BUK];
__device__ int    g_part[NPART];
__device__ int    g_partoff[NPART + 1];
__device__ int    g_pid[N_MAX];
__device__ int    g_nblk;
__device__ int    g_dstart[MAXBLK];
__device__ int    g_dend[MAXBLK];
__device__ int    g_dbatch[MAXBLK];
__device__ int4   g_iw[N_MAX];        // packed neighbor indices (i0,i1,i2,0)
__device__ float4 g_wv[N_MAX];        // packed weights (w0,w1,w2,0)

// ---- init: clear heads + bitmask + bucket counters ----
__global__ void k_init() {
    int i = blockIdx.x * blockDim.x + threadIdx.x;
    int stride = gridDim.x * blockDim.x;
    for (int k = i; k < NB * CELLS; k += stride) g_head[k] = -1;
    for (int k = i; k < NB * BMW; k += stride) g_bm[k] = 0u;
    for (int k = i; k < BUK; k += stride) g_bcnt[k] = 0;
}

__device__ __forceinline__ int cell_of(float v) {
    return min(63, max(0, (int)floorf(fmaf(v, 20.0f, 32.0f))));
}
__device__ __forceinline__ int key_of(int b, const float* pc, int i) {
    int cx = cell_of(pc[3 * i]);
    int cy = cell_of(pc[3 * i + 1]);
    int cz = cell_of(pc[3 * i + 2]);
    return (b << 14) | (cz << 8) | (cy << 2) | (cx >> 4);
}

// ---- fused: voxel build (i < M) + point histogram (i < N) ----
__global__ void k_build_hist(const int* __restrict__ indices, int M,
                             const float* __restrict__ pc,
                             const int* __restrict__ bids, int N) {
    int i = blockIdx.x * blockDim.x + threadIdx.x;
    if (i < M) {
        int4 v = ((const int4*)indices)[i];
        // replicate reference rounding: mul, add, add as separate ops (no FMA)
        float qx = __fadd_rn(__fadd_rn(__fmul_rn((float)v.y, 0.05f), -1.6f), 0.025f);
        float qy = __fadd_rn(__fadd_rn(__fmul_rn((float)v.z, 0.05f), -1.6f), 0.025f);
        float qz = __fadd_rn(__fadd_rn(__fmul_rn((float)v.w, 0.05f), -1.6f), 0.025f);
        int cell = (((v.w << 6) | v.z) << 6) | v.y;   // X fastest
        int old = atomicExch(&g_head[v.x * CELLS + cell], i);
        g_qpos[i] = make_float4(qx, qy, qz, __int_as_float(old));
        atomicOr(&g_bm[v.x * BMW + (cell >> 5)], 1u << (cell & 31));
    }
    if (i < N) atomicAdd(&g_bcnt[key_of(bids[i], pc, i)], 1);
}

// ---- compact: head entry of each occupied cell -> direct-mapped g_cell ----
__global__ void k_compact(const int* __restrict__ indices, int M) {
    int i = blockIdx.x * blockDim.x + threadIdx.x;
    if (i >= M) return;
    int4 v = ((const int4*)indices)[i];
    int cell = (((v.w << 6) | v.z) << 6) | v.y;
    int slot = v.x * CELLS + cell;
    if (g_head[slot] == i) {
        float4 q = g_qpos[i];
        int next = __float_as_int(q.w);
        int wbits = i | (next >= 0 ? CHAINF : 0);
        g_cell[slot] = make_float4(q.x, q.y, q.z, __int_as_float(wbits));
    }
}

// ---- scan stage 1: per-partition sums ----
__global__ void __launch_bounds__(256) k_part() {
    __shared__ int s[256];
    int t = threadIdx.x;
    s[t] = g_bcnt[blockIdx.x * 256 + t];
    __syncthreads();
    for (int o = 128; o > 0; o >>= 1) {
        if (t < o) s[t] += s[t + o];
        __syncthreads();
    }
    if (t == 0) g_part[blockIdx.x] = s[0];
}

// ---- scan stage 2: exclusive scan of partials + block descriptors ----
__global__ void __launch_bounds__(256) k_top() {
    __shared__ int s[257];
    int t = threadIdx.x;
    s[t] = g_part[t];
    __syncthreads();
    for (int o = 1; o < 256; o <<= 1) {     // race-free Hillis-Steele
        int v = (t >= o) ? s[t - o] : 0;
        __syncthreads();
        s[t] += v;
        __syncthreads();
    }
    int total = s[255];
    int excl = (t == 0) ? 0 : s[t - 1];
    __syncthreads();
    s[t] = excl;
    if (t == 0) s[256] = total;
    g_partoff[t] = excl;
    if (t == 0) g_partoff[256] = total;
    __syncthreads();
    if (t == 0) {
        int dt = 0;
        for (int b = 0; b < NB; b++) {
            int cbase = s[b * 64];
            int cend  = s[(b + 1) * 64];
            for (int k = cbase; k < cend; k += BPTS) {
                g_dstart[dt] = k;
                g_dend[dt]   = min(cend, k + BPTS);
                g_dbatch[dt] = b;
                dt++;
            }
        }
        g_nblk = dt;
    }
}

// ---- scan stage 3: per-bucket exclusive offsets ----
__global__ void __launch_bounds__(256) k_off() {
    __shared__ int s[256];
    int t = threadIdx.x;
    int base = blockIdx.x * 256;
    int v0 = g_bcnt[base + t];
    s[t] = v0;
    __syncthreads();
    for (int o = 1; o < 256; o <<= 1) {
        int v = (t >= o) ? s[t - o] : 0;
        __syncthreads();
        s[t] += v;
        __syncthreads();
    }
    g_bcur[base + t] = g_partoff[blockIdx.x] + s[t] - v0;
}

__global__ void k_scatterp(const float* __restrict__ pc, const int* __restrict__ bids, int N) {
    int i = blockIdx.x * blockDim.x + threadIdx.x;
    if (i < N) {
        int pos = atomicAdd(&g_bcur[key_of(bids[i], pc, i)], 1);
        g_pid[pos] = i;
    }
}

// tie-aware top-3 insert: (d, idx) lexicographic, matches stable jax top_k
#define INS3(dd, e)                                                          \
    do {                                                                     \
        float _d = (dd); int _e = (e);                                       \
        if (_d < D2 || (_d == D2 && _e < I2)) {                              \
            if (_d < D1 || (_d == D1 && _e < I1)) {                          \
                if (_d < D0 || (_d == D0 && _e < I0)) {                      \
                    D2 = D1; I2 = I1; D1 = D0; I1 = I0; D0 = _d; I0 = _e;    \
                } else { D2 = D1; I2 = I1; D1 = _d; I1 = _e; }               \
            } else { D2 = _d; I2 = _e; }                                     \
        }                                                                    \
    } while (0)

// test one bitmask row (z,y) against mask mk; direct-mapped cell lookups
#define PROW(zz, yy, mk)                                                     \
    do {                                                                     \
        unsigned long long rowm =                                            \
            *(const unsigned long long*)&sbm[((((zz) << 6) + (yy)) << 1)];   \
        rowm &= (mk);                                                        \
        while (rowm) {                                                       \
            int xb = __ffsll((long long)rowm) - 1;                           \
            rowm &= rowm - 1;                                                \
            int cell = (((((zz) << 6) + (yy)) << 6) + xb);                   \
            float4 qq = g_cell[hb + cell];                                   \
            int wi = __float_as_int(qq.w);                                   \
            int qi = wi & IDXM;                                              \
            float ddx = px - qq.x, ddy = py - qq.y, ddz = pz - qq.z;         \
            float dd = fmaf(ddx, ddx, fmaf(ddy, ddy, ddz * ddz));            \
            INS3(dd, qi);                                                    \
            if (wi & CHAINF) {                                               \
                int e = __float_as_int(g_qpos[qi].w);                        \
                while (e >= 0) {                                             \
                    float4 q2 = g_qpos[e];                                   \
                    float ex = px - q2.x, ey = py - q2.y, ez = pz - q2.z;    \
                    float d2c = fmaf(ex, ex, fmaf(ey, ey, ez * ez));         \
                    INS3(d2c, e);                                            \
                    e = __float_as_int(q2.w);                                \
                }                                                            \
            }                                                                \
        }                                                                    \
    } while (0)

__global__ void __launch_bounds__(TPB) nn_kernel(const float* __restrict__ pc,
                                                 const int* __restrict__ indices,
                                                 int M) {
    __shared__ unsigned int sbm[BMW];
    if (blockIdx.x >= g_nblk) return;

    int b  = g_dbatch[blockIdx.x];
    int pS = g_dstart[blockIdx.x];
    int pE = g_dend[blockIdx.x];
    int hb = b * CELLS;

    // stage 32KB bitmask with uint4 loads (2048 vecs / 512 threads = 4 each)
    {
        const uint4* src = (const uint4*)&g_bm[b * BMW];
        uint4* dst = (uint4*)sbm;
        for (int i = threadIdx.x; i < BMW / 4; i += TPB) dst[i] = src[i];
    }
    __syncthreads();

    int ni = pS + threadIdx.x;
    if (ni >= pE) return;
    int pid = g_pid[ni];
    float px = pc[3 * pid], py = pc[3 * pid + 1], pz = pc[3 * pid + 2];

    int cx = cell_of(px);
    int cy = cell_of(py);
    int cz = cell_of(pz);

    float D0 = BIGF, D1 = BIGF, D2 = BIGF;
    int   I0 = 0,    I1 = 0,    I2 = 0;

    for (int r = 0; r <= 63; r++) {
        if (r > 0 && D2 < BIGF) {
            float br = ((float)r - 0.5f) * 0.05f;
            if (D2 + 1e-6f < br * br) break;   // no unscanned cell can beat top-3
        }
        if (r == 0) {
            PROW(cz, cy, 1ull << cx);
            continue;
        }
        int xlo = max(cx - r, 0), xhi = min(cx + r, 63);
        unsigned long long fm =
            (xhi - xlo == 63) ? ~0ull
                              : (((1ull << (xhi - xlo + 1)) - 1ull) << xlo);
        unsigned long long pm = 0ull;
        if (cx - r >= 0)  pm |= 1ull << (cx - r);
        if (cx + r <= 63) pm |= 1ull << (cx + r);

        int ylo = max(cy - r, 0), yhi = min(cy + r, 63);
        // faces z = cz +- r : full (y,x) square
        if (cz - r >= 0)  { int z = cz - r; for (int y = ylo; y <= yhi; y++) PROW(z, y, fm); }
        if (cz + r <= 63) { int z = cz + r; for (int y = ylo; y <= yhi; y++) PROW(z, y, fm); }
        // edges y = cy +- r, |dz| < r : full x rows
        int z0 = max(cz - r + 1, 0), z1 = min(cz + r - 1, 63);
        if (cy - r >= 0)  { int y = cy - r; for (int z = z0; z <= z1; z++) PROW(z, y, fm); }
        if (cy + r <= 63) { int y = cy + r; for (int z = z0; z <= z1; z++) PROW(z, y, fm); }
        // interior: x = cx +- r only
        if (pm) {
            int y0 = max(cy - r + 1, 0), y1 = min(cy + r - 1, 63);
            for (int z = z0; z <= z1; z++)
                for (int y = y0; y <= y1; y++) PROW(z, y, pm);
        }
    }

    // fallback: exact full 4D scan (cross-batch possible only if D2 >= 1.0)
    if (D2 >= 1.0f) {
        float pb = (float)b;
        D0 = BIGF; D1 = BIGF; D2 = BIGF; I0 = 0; I1 = 0; I2 = 0;
        for (int i = 0; i < M; i++) {
            int4 v = ((const int4*)indices)[i];
            float qb = (float)v.x;
            float qx = __fadd_rn(__fadd_rn(__fmul_rn((float)v.y, 0.05f), -1.6f), 0.025f);
            float qy = __fadd_rn(__fadd_rn(__fmul_rn((float)v.z, 0.05f), -1.6f), 0.025f);
            float qz = __fadd_rn(__fadd_rn(__fmul_rn((float)v.w, 0.05f), -1.6f), 0.025f);
            float dx = px - qx, dy = py - qy, dz = pz - qz, db = pb - qb;
            float dd = fmaf(dx, dx, fmaf(dy, dy, fmaf(dz, dz, db * db)));
            INS3(dd, i);
        }
    }

    float r0 = 1.0f / (D0 + 1e-8f);
    float r1 = 1.0f / (D1 + 1e-8f);
    float r2 = 1.0f / (D2 + 1e-8f);
    float s = r0 + r1 + r2;
    g_wv[pid] = make_float4(r0 / s, r1 / s, r2 / s, 0.0f);
    g_iw[pid] = make_int4(I0, I1, I2, 0);
}

// ---- weighted gather-interpolate: 8 threads/point, 2 float4 chains each ----
__global__ void interp_kernel(const float* __restrict__ feats,
                              float* __restrict__ out, int N, int C) {
    int t = blockIdx.x * blockDim.x + threadIdx.x;
    int n = t >> 3;            // 8 threads per point (C = 64)
    int c = t & 7;             // this thread covers float4 columns c and c+8
    if (n >= N) return;

    int4   iv = g_iw[n];
    float4 wv = g_wv[n];
    const float4* f = (const float4*)feats;
    int C4 = C >> 2;           // 16
    long ba = (long)iv.x * C4 + c;
    long bb = (long)iv.y * C4 + c;
    long bc = (long)iv.z * C4 + c;

    float4 a0 = f[ba],     b0 = f[bb],     c0 = f[bc];
    float4 a1 = f[ba + 8], b1 = f[bb + 8], c1 = f[bc + 8];

    float4 o0, o1;
    o0.x = wv.x * a0.x + wv.y * b0.x + wv.z * c0.x;
    o0.y = wv.x * a0.y + wv.y * b0.y + wv.z * c0.y;
    o0.z = wv.x * a0.z + wv.y * b0.z + wv.z * c0.z;
    o0.w = wv.x * a0.w + wv.y * b0.w + wv.z * c0.w;
    o1.x = wv.x * a1.x + wv.y * b1.x + wv.z * c1.x;
    o1.y = wv.x * a1.y + wv.y * b1.y + wv.z * c1.y;
    o1.z = wv.x * a1.z + wv.y * b1.z + wv.z * c1.z;
    o1.w = wv.x * a1.w + wv.y * b1.w + wv.z * c1.w;

    float4* ov = (float4*)out;
    ov[(long)n * C4 + c]     = o0;
    ov[(long)n * C4 + c + 8] = o1;
}

extern "C" void kernel_launch(void* const* d_in, const int* in_sizes, int n_in,
                              void* d_out, int out_size) {
    const float* features = (const float*)d_in[0];  // (M, C) f32
    const int*   indices  = (const int*)d_in[1];    // (M, 4) i32
    const float* pc       = (const float*)d_in[2];  // (N, 3) f32
    const int*   bids     = (const int*)d_in[3];    // (N,)   i32

    int M = in_sizes[1] / 4;
    int C = in_sizes[0] / M;
    int N = in_sizes[3];
    int mx = (M > N) ? M : N;

    k_init<<<1024, 256>>>();
    k_build_hist<<<(mx + 255) / 256, 256>>>(indices, M, pc, bids, N);
    k_compact<<<(M + 255) / 256, 256>>>(indices, M);
    k_part<<<NPART, 256>>>();
    k_top<<<1, 256>>>();
    k_off<<<NPART, 256>>>();
    k_scatterp<<<(N + 255) / 256, 256>>>(pc, bids, N);

    int maxblk = (N + BPTS - 1) / BPTS + NB;
    nn_kernel<<<maxblk, TPB>>>(pc, indices, M);

    interp_kernel<<<(N * 8 + 255) / 256, 256>>>(features, (float*)d_out, N, C);
}

// round 11
// speedup vs baseline: 1.8848x; 1.0008x over previous
#include <cuda_runtime.h>

// ---------------------------------------------------------------------------
// Voxel2Point via occupancy-grid 3-NN (R11 = R10 with launch fusion):
//   7 launches: init, build+hist, part+compact, off(+top inline), scatter,
//   nn, interp. Hot kernels identical to R10.
//   - per-batch 64^3 occupancy bitmask staged in SMEM; Chebyshev shells with
//     provable stop bound; direct-mapped g_cell (one LDG.128 per cell)
//   - points spatially sorted by (batch, cz, cy, cx>>4)
//   - tie-aware top-3 == stable jax top_k; exact 4D fallback if D2 >= 1.0
// ---------------------------------------------------------------------------

#define NB     4
#define M_MAX  16384
#define N_MAX  131072
#define TPB    512
#define BPTS   512
#define MAXBLK (N_MAX / BPTS + NB)
#define BIGF   1e30f
#define CELLS  262144          // 64^3
#define BMW    8192            // bitmask words per batch (64^3 / 32)
#define BUK    65536           // sort buckets: (b, cz, cy, cx>>4)
#define NPART  256             // scan partitions (BUK / 256)
#define CHAINF 0x40000000      // "cell has more entries" flag in g_cell.w
#define IDXM   0x3FFF          // index mask (M <= 16384)

__device__ int    g_head[NB * CELLS];
__device__ float4 g_qpos[M_MAX];      // x,y,z = center; w = next index bits
__device__ float4 g_cell[NB * CELLS]; // head entry — bitmask-guarded, no init
__device__ unsigned int g_bm[NB * BMW];
__device__ int    g_bcnt[BUK];
__device__ int    g_bcur[BUK];
__device__ int    g_part[NPART];
__device__ int    g_pid[N_MAX];
__device__ int    g_nblk;
__device__ int    g_dstart[MAXBLK];
__device__ int    g_dend[MAXBLK];
__device__ int    g_dbatch[MAXBLK];
__device__ int4   g_iw[N_MAX];        // packed neighbor indices (i0,i1,i2,0)
__device__ float4 g_wv[N_MAX];        // packed weights (w0,w1,w2,0)

// ---- init: clear heads + bitmask + bucket counters ----
__global__ void k_init() {
    int i = blockIdx.x * blockDim.x + threadIdx.x;
    int stride = gridDim.x * blockDim.x;
    for (int k = i; k < NB * CELLS; k += stride) g_head[k] = -1;
    for (int k = i; k < NB * BMW; k += stride) g_bm[k] = 0u;
    for (int k = i; k < BUK; k += stride) g_bcnt[k] = 0;
}

__device__ __forceinline__ int cell_of(float v) {
    return min(63, max(0, (int)floorf(fmaf(v, 20.0f, 32.0f))));
}
__device__ __forceinline__ int key_of(int b, const float* pc, int i) {
    int cx = cell_of(pc[3 * i]);
    int cy = cell_of(pc[3 * i + 1]);
    int cz = cell_of(pc[3 * i + 2]);
    return (b << 14) | (cz << 8) | (cy << 2) | (cx >> 4);
}

// ---- fused: voxel build (i < M) + point histogram (i < N) ----
__global__ void k_build_hist(const int* __restrict__ indices, int M,
                             const float* __restrict__ pc,
                             const int* __restrict__ bids, int N) {
    int i = blockIdx.x * blockDim.x + threadIdx.x;
    if (i < M) {
        int4 v = ((const int4*)indices)[i];
        // replicate reference rounding: mul, add, add as separate ops (no FMA)
        float qx = __fadd_rn(__fadd_rn(__fmul_rn((float)v.y, 0.05f), -1.6f), 0.025f);
        float qy = __fadd_rn(__fadd_rn(__fmul_rn((float)v.z, 0.05f), -1.6f), 0.025f);
        float qz = __fadd_rn(__fadd_rn(__fmul_rn((float)v.w, 0.05f), -1.6f), 0.025f);
        int cell = (((v.w << 6) | v.z) << 6) | v.y;   // X fastest
        int old = atomicExch(&g_head[v.x * CELLS + cell], i);
        g_qpos[i] = make_float4(qx, qy, qz, __int_as_float(old));
        atomicOr(&g_bm[v.x * BMW + (cell >> 5)], 1u << (cell & 31));
    }
    if (i < N) atomicAdd(&g_bcnt[key_of(bids[i], pc, i)], 1);
}

// ---- fused: partition sums (blocks [0,NPART)) + cell compact (rest) ----
__global__ void __launch_bounds__(256) k_part_compact(const int* __restrict__ indices, int M) {
    if (blockIdx.x < NPART) {
        __shared__ int s[256];
        int t = threadIdx.x;
        s[t] = g_bcnt[blockIdx.x * 256 + t];
        __syncthreads();
        for (int o = 128; o > 0; o >>= 1) {
            if (t < o) s[t] += s[t + o];
            __syncthreads();
        }
        if (t == 0) g_part[blockIdx.x] = s[0];
    } else {
        int i = (blockIdx.x - NPART) * 256 + threadIdx.x;
        if (i >= M) return;
        int4 v = ((const int4*)indices)[i];
        int cell = (((v.w << 6) | v.z) << 6) | v.y;
        int slot = v.x * CELLS + cell;
        if (g_head[slot] == i) {
            float4 q = g_qpos[i];
            int next = __float_as_int(q.w);
            int wbits = i | (next >= 0 ? CHAINF : 0);
            g_cell[slot] = make_float4(q.x, q.y, q.z, __int_as_float(wbits));
        }
    }
}

// ---- fused top+off: every block scans the 256 partials locally, then its
//      own 256 bucket counts; block 0 also emits nn block descriptors ----
__global__ void __launch_bounds__(256) k_off2() {
    __shared__ int ps[256];      // inclusive scan of partials
    __shared__ int s[256];       // inclusive scan of own bucket counts
    int t = threadIdx.x;

    ps[t] = g_part[t];
    __syncthreads();
    for (int o = 1; o < 256; o <<= 1) {         // race-free Hillis-Steele
        int v = (t >= o) ? ps[t - o] : 0;
        __syncthreads();
        ps[t] += v;
        __syncthreads();
    }
    int mybase = (blockIdx.x == 0) ? 0 : ps[blockIdx.x - 1];

    int base = blockIdx.x * 256;
    int v0 = g_bcnt[base + t];
    s[t] = v0;
    __syncthreads();
    for (int o = 1; o < 256; o <<= 1) {
        int v = (t >= o) ? s[t - o] : 0;
        __syncthreads();
        s[t] += v;
        __syncthreads();
    }
    g_bcur[base + t] = mybase + s[t] - v0;      // exclusive offset

    if (blockIdx.x == 0 && t == 0) {
        // batch b spans part chunks [b*64, (b+1)*64): exclusive bases from ps
        int dt = 0;
        for (int b = 0; b < NB; b++) {
            int cbase = (b == 0) ? 0 : ps[b * 64 - 1];
            int cend  = ps[(b + 1) * 64 - 1];
            for (int k = cbase; k < cend; k += BPTS) {
                g_dstart[dt] = k;
                g_dend[dt]   = min(cend, k + BPTS);
                g_dbatch[dt] = b;
                dt++;
            }
        }
        g_nblk = dt;
    }
}

__global__ void k_scatterp(const float* __restrict__ pc, const int* __restrict__ bids, int N) {
    int i = blockIdx.x * blockDim.x + threadIdx.x;
    if (i < N) {
        int pos = atomicAdd(&g_bcur[key_of(bids[i], pc, i)], 1);
        g_pid[pos] = i;
    }
}

// tie-aware top-3 insert: (d, idx) lexicographic, matches stable jax top_k
#define INS3(dd, e)                                                          \
    do {                                                                     \
        float _d = (dd); int _e = (e);                                       \
        if (_d < D2 || (_d == D2 && _e < I2)) {                              \
            if (_d < D1 || (_d == D1 && _e < I1)) {                          \
                if (_d < D0 || (_d == D0 && _e < I0)) {                      \
                    D2 = D1; I2 = I1; D1 = D0; I1 = I0; D0 = _d; I0 = _e;    \
                } else { D2 = D1; I2 = I1; D1 = _d; I1 = _e; }               \
            } else { D2 = _d; I2 = _e; }                                     \
        }                                                                    \
    } while (0)

// test one bitmask row (z,y) against mask mk; direct-mapped cell lookups
#define PROW(zz, yy, mk)                                                     \
    do {                                                                     \
        unsigned long long rowm =                                            \
            *(const unsigned long long*)&sbm[((((zz) << 6) + (yy)) << 1)];   \
        rowm &= (mk);                                                        \
        while (rowm) {                                                       \
            int xb = __ffsll((long long)rowm) - 1;                           \
            rowm &= rowm - 1;                                                \
            int cell = (((((zz) << 6) + (yy)) << 6) + xb);                   \
            float4 qq = g_cell[hb + cell];                                   \
            int wi = __float_as_int(qq.w);                                   \
            int qi = wi & IDXM;                                              \
            float ddx = px - qq.x, ddy = py - qq.y, ddz = pz - qq.z;         \
            float dd = fmaf(ddx, ddx, fmaf(ddy, ddy, ddz * ddz));            \
            INS3(dd, qi);                                                    \
            if (wi & CHAINF) {                                               \
                int e = __float_as_int(g_qpos[qi].w);                        \
                while (e >= 0) {                                             \
                    float4 q2 = g_qpos[e];                                   \
                    float ex = px - q2.x, ey = py - q2.y, ez = pz - q2.z;    \
                    float d2c = fmaf(ex, ex, fmaf(ey, ey, ez * ez));         \
                    INS3(d2c, e);                                            \
                    e = __float_as_int(q2.w);                                \
                }                                                            \
            }                                                                \
        }                                                                    \
    } while (0)

__global__ void __launch_bounds__(TPB) nn_kernel(const float* __restrict__ pc,
                                                 const int* __restrict__ indices,
                                                 int M) {
    __shared__ unsigned int sbm[BMW];
    if (blockIdx.x >= g_nblk) return;

    int b  = g_dbatch[blockIdx.x];
    int pS = g_dstart[blockIdx.x];
    int pE = g_dend[blockIdx.x];
    int hb = b * CELLS;

    {
        const uint4* src = (const uint4*)&g_bm[b * BMW];
        uint4* dst = (uint4*)sbm;
        for (int i = threadIdx.x; i < BMW / 4; i += TPB) dst[i] = src[i];
    }
    __syncthreads();

    int ni = pS + threadIdx.x;
    if (ni >= pE) return;
    int pid = g_pid[ni];
    float px = pc[3 * pid], py = pc[3 * pid + 1], pz = pc[3 * pid + 2];

    int cx = cell_of(px);
    int cy = cell_of(py);
    int cz = cell_of(pz);

    float D0 = BIGF, D1 = BIGF, D2 = BIGF;
    int   I0 = 0,    I1 = 0,    I2 = 0;

    for (int r = 0; r <= 63; r++) {
        if (r > 0 && D2 < BIGF) {
            float br = ((float)r - 0.5f) * 0.05f;
            if (D2 + 1e-6f < br * br) break;   // no unscanned cell can beat top-3
        }
        if (r == 0) {
            PROW(cz, cy, 1ull << cx);
            continue;
        }
        int xlo = max(cx - r, 0), xhi = min(cx + r, 63);
        unsigned long long fm =
            (xhi - xlo == 63) ? ~0ull
                              : (((1ull << (xhi - xlo + 1)) - 1ull) << xlo);
        unsigned long long pm = 0ull;
        if (cx - r >= 0)  pm |= 1ull << (cx - r);
        if (cx + r <= 63) pm |= 1ull << (cx + r);

        int ylo = max(cy - r, 0), yhi = min(cy + r, 63);
        // faces z = cz +- r : full (y,x) square
        if (cz - r >= 0)  { int z = cz - r; for (int y = ylo; y <= yhi; y++) PROW(z, y, fm); }
        if (cz + r <= 63) { int z = cz + r; for (int y = ylo; y <= yhi; y++) PROW(z, y, fm); }
        // edges y = cy +- r, |dz| < r : full x rows
        int z0 = max(cz - r + 1, 0), z1 = min(cz + r - 1, 63);
        if (cy - r >= 0)  { int y = cy - r; for (int z = z0; z <= z1; z++) PROW(z, y, fm); }
        if (cy + r <= 63) { int y = cy + r; for (int z = z0; z <= z1; z++) PROW(z, y, fm); }
        // interior: x = cx +- r only
        if (pm) {
            int y0 = max(cy - r + 1, 0), y1 = min(cy + r - 1, 63);
            for (int z = z0; z <= z1; z++)
                for (int y = y0; y <= y1; y++) PROW(z, y, pm);
        }
    }

    // fallback: exact full 4D scan (cross-batch possible only if D2 >= 1.0)
    if (D2 >= 1.0f) {
        float pb = (float)b;
        D0 = BIGF; D1 = BIGF; D2 = BIGF; I0 = 0; I1 = 0; I2 = 0;
        for (int i = 0; i < M; i++) {
            int4 v = ((const int4*)indices)[i];
            float qb = (float)v.x;
            float qx = __fadd_rn(__fadd_rn(__fmul_rn((float)v.y, 0.05f), -1.6f), 0.025f);
            float qy = __fadd_rn(__fadd_rn(__fmul_rn((float)v.z, 0.05f), -1.6f), 0.025f);
            float qz = __fadd_rn(__fadd_rn(__fmul_rn((float)v.w, 0.05f), -1.6f), 0.025f);
            float dx = px - qx, dy = py - qy, dz = pz - qz, db = pb - qb;
            float dd = fmaf(dx, dx, fmaf(dy, dy, fmaf(dz, dz, db * db)));
            INS3(dd, i);
        }
    }

    float r0 = 1.0f / (D0 + 1e-8f);
    float r1 = 1.0f / (D1 + 1e-8f);
    float r2 = 1.0f / (D2 + 1e-8f);
    float s = r0 + r1 + r2;
    g_wv[pid] = make_float4(r0 / s, r1 / s, r2 / s, 0.0f);
    g_iw[pid] = make_int4(I0, I1, I2, 0);
}

// ---- weighted gather-interpolate: 8 threads/point, 2 float4 chains each ----
__global__ void interp_kernel(const float* __restrict__ feats,
                              float* __restrict__ out, int N, int C) {
    int t = blockIdx.x * blockDim.x + threadIdx.x;
    int n = t >> 3;            // 8 threads per point (C = 64)
    int c = t & 7;             // this thread covers float4 columns c and c+8
    if (n >= N) return;

    int4   iv = g_iw[n];
    float4 wv = g_wv[n];
    const float4* f = (const float4*)feats;
    int C4 = C >> 2;           // 16
    long ba = (long)iv.x * C4 + c;
    long bb = (long)iv.y * C4 + c;
    long bc = (long)iv.z * C4 + c;

    float4 a0 = f[ba],     b0 = f[bb],     c0 = f[bc];
    float4 a1 = f[ba + 8], b1 = f[bb + 8], c1 = f[bc + 8];

    float4 o0, o1;
    o0.x = wv.x * a0.x + wv.y * b0.x + wv.z * c0.x;
    o0.y = wv.x * a0.y + wv.y * b0.y + wv.z * c0.y;
    o0.z = wv.x * a0.z + wv.y * b0.z + wv.z * c0.z;
    o0.w = wv.x * a0.w + wv.y * b0.w + wv.z * c0.w;
    o1.x = wv.x * a1.x + wv.y * b1.x + wv.z * c1.x;
    o1.y = wv.x * a1.y + wv.y * b1.y + wv.z * c1.y;
    o1.z = wv.x * a1.z + wv.y * b1.z + wv.z * c1.z;
    o1.w = wv.x * a1.w + wv.y * b1.w + wv.z * c1.w;

    float4* ov = (float4*)out;
    ov[(long)n * C4 + c]     = o0;
    ov[(long)n * C4 + c + 8] = o1;
}

extern "C" void kernel_launch(void* const* d_in, const int* in_sizes, int n_in,
                              void* d_out, int out_size) {
    const float* features = (const float*)d_in[0];  // (M, C) f32
    const int*   indices  = (const int*)d_in[1];    // (M, 4) i32
    const float* pc       = (const float*)d_in[2];  // (N, 3) f32
    const int*   bids     = (const int*)d_in[3];    // (N,)   i32

    int M = in_sizes[1] / 4;
    int C = in_sizes[0] / M;
    int N = in_sizes[3];
    int mx = (M > N) ? M : N;

    k_init<<<1024, 256>>>();
    k_build_hist<<<(mx + 255) / 256, 256>>>(indices, M, pc, bids, N);
    k_part_compact<<<NPART + (M + 255) / 256, 256>>>(indices, M);
    k_off2<<<NPART, 256>>>();
    k_scatterp<<<(N + 255) / 256, 256>>>(pc, bids, N);

    int maxblk = (N + BPTS - 1) / BPTS + NB;
    nn_kernel<<<maxblk, TPB>>>(pc, indices, M);

    interp_kernel<<<(N * 8 + 255) / 256, 256>>>(features, (float*)d_out, N, C);
}